// round 5
// baseline (speedup 1.0000x reference)
#include <cuda_runtime.h>

// Problem constants
#define T_  4
#define B_  8192
#define D_  1024
#define U_  512
#define E_  8
#define UE  4096      // U*E
#define NG0 104       // 4*16 + 40 gate columns at level 0

// ---------------------------------------------------------------------------
// Scratch (device globals; allocation APIs are forbidden)
// ---------------------------------------------------------------------------
__device__ float g_H[5ull * B_ * UE];                    // expert outputs, reused by both levels (671 MB)
__device__ float g_g0[(size_t)T_ * B_ * 16];             // level-0 task gates
__device__ float g_gs[(size_t)B_ * 40];                  // level-0 shared gate
__device__ float g_task0[(size_t)T_ * B_ * U_];          // level-0 task outputs
__device__ float g_share[(size_t)B_ * U_];               // level-0 shared output
__device__ float g_g1[(size_t)T_ * B_ * 16];             // level-1 task gates

// ---------------------------------------------------------------------------
// Expert GEMM: for each slot t in [0,5): H[t] = relu(A_t (MxK) @ B_t (Kx4096) + bias_t)
// B_t layout: B[k][n] = base_t[k*4096 + n]   (true for ew0/ews0/ew1/ews1)
// Tile: 128x128x16, 8x8 per thread (N packed in f32x2 pairs), 256 threads,
// double-buffered SMEM.
// ---------------------------------------------------------------------------
struct GemmArgs {
    const float* A[5];
    const float* Bm[5];
    const float* bias[5];
    float*       H;
    int          K;
};

__global__ __launch_bounds__(256, 2) void expert_gemm(GemmArgs args) {
    const int t  = blockIdx.x >> 5;            // 32 n-tiles of 128 per slot
    const int n0 = (blockIdx.x & 31) << 7;
    const int m0 = blockIdx.y << 7;
    const int K  = args.K;

    const float* __restrict__ A    = args.A[t];
    const float* __restrict__ Bmat = args.Bm[t];

    __shared__ float As[2][16][128];   // transposed: As[k][m]
    __shared__ float Bs[2][16][128];   // Bs[k][n]

    const int tid = threadIdx.x;
    const int tx  = tid & 15;
    const int ty  = tid >> 4;

    // cooperative load mapping
    const int am = tid >> 2;           // 0..63 (A row within tile, +64 for 2nd)
    const int ak = (tid & 3) << 2;     // 0,4,8,12
    const int bk = tid >> 5;           // 0..7  (B k within tile, +8 for 2nd)
    const int bn = (tid & 31) << 2;    // 0..124

    const float* Ap  = A + (size_t)(m0 + am) * K + ak;
    const float* Ap2 = Ap + (size_t)64 * K;
    const float* Bp  = Bmat + (size_t)bk * UE + n0 + bn;
    const float* Bp2 = Bp + (size_t)8 * UE;

    // accumulators: 8 rows x 4 f32x2 pairs (= 8 cols)
    unsigned long long acc[8][4];
#pragma unroll
    for (int i = 0; i < 8; i++)
#pragma unroll
        for (int j = 0; j < 4; j++) acc[i][j] = 0ull;

    // prologue: tile 0 -> buffer 0
    {
        float4 a0 = *(const float4*)Ap;
        float4 a1 = *(const float4*)Ap2;
        float4 b0 = *(const float4*)Bp;
        float4 b1 = *(const float4*)Bp2;
        As[0][ak + 0][am] = a0.x; As[0][ak + 1][am] = a0.y;
        As[0][ak + 2][am] = a0.z; As[0][ak + 3][am] = a0.w;
        As[0][ak + 0][am + 64] = a1.x; As[0][ak + 1][am + 64] = a1.y;
        As[0][ak + 2][am + 64] = a1.z; As[0][ak + 3][am + 64] = a1.w;
        *(float4*)&Bs[0][bk][bn]     = b0;
        *(float4*)&Bs[0][bk + 8][bn] = b1;
    }
    __syncthreads();

    int buf = 0;
    const int nk = K >> 4;
    for (int kt = 0; kt < nk; kt++) {
        float4 a0, a1, b0, b1;
        const bool more = (kt + 1 < nk);
        if (more) {
            const int ko = (kt + 1) << 4;
            a0 = *(const float4*)(Ap  + ko);
            a1 = *(const float4*)(Ap2 + ko);
            b0 = *(const float4*)(Bp  + (size_t)ko * UE);
            b1 = *(const float4*)(Bp2 + (size_t)ko * UE);
        }
#pragma unroll
        for (int kk = 0; kk < 16; kk++) {
            float af[8];
            *(float4*)(af)     = *(const float4*)&As[buf][kk][ty << 3];
            *(float4*)(af + 4) = *(const float4*)&As[buf][kk][(ty << 3) + 4];
            unsigned long long bf[4];
            *(ulonglong2*)(bf)     = *(const ulonglong2*)&Bs[buf][kk][tx << 3];
            *(ulonglong2*)(bf + 2) = *(const ulonglong2*)&Bs[buf][kk][(tx << 3) + 4];
#pragma unroll
            for (int i = 0; i < 8; i++) {
                unsigned long long a2;
                unsigned int ai = __float_as_uint(af[i]);
                asm("mov.b64 %0, {%1, %1};" : "=l"(a2) : "r"(ai));
#pragma unroll
                for (int j = 0; j < 4; j++)
                    asm("fma.rn.f32x2 %0, %1, %2, %0;"
                        : "+l"(acc[i][j]) : "l"(a2), "l"(bf[j]));
            }
        }
        if (more) {
            buf ^= 1;
            As[buf][ak + 0][am] = a0.x; As[buf][ak + 1][am] = a0.y;
            As[buf][ak + 2][am] = a0.z; As[buf][ak + 3][am] = a0.w;
            As[buf][ak + 0][am + 64] = a1.x; As[buf][ak + 1][am + 64] = a1.y;
            As[buf][ak + 2][am + 64] = a1.z; As[buf][ak + 3][am + 64] = a1.w;
            *(float4*)&Bs[buf][bk][bn]     = b0;
            *(float4*)&Bs[buf][bk + 8][bn] = b1;
            __syncthreads();
        }
    }

    // epilogue: bias + relu, store H[t][m][n]
    const float* __restrict__ bias = args.bias[t] + n0 + (tx << 3);
    float bv[8];
    *(float4*)(bv)     = *(const float4*)(bias);
    *(float4*)(bv + 4) = *(const float4*)(bias + 4);

    float* Hp = args.H + ((size_t)t * B_ + (size_t)(m0 + (ty << 3))) * UE + n0 + (tx << 3);
#pragma unroll
    for (int i = 0; i < 8; i++) {
        float out[8];
#pragma unroll
        for (int j = 0; j < 4; j++) {
            unsigned int lo = (unsigned int)(acc[i][j]);
            unsigned int hi = (unsigned int)(acc[i][j] >> 32);
            out[2 * j]     = __uint_as_float(lo) + bv[2 * j];
            out[2 * j + 1] = __uint_as_float(hi) + bv[2 * j + 1];
        }
#pragma unroll
        for (int j = 0; j < 8; j++) out[j] = fmaxf(out[j], 0.0f);
        *(float4*)(Hp + (size_t)i * UE)     = *(float4*)(out);
        *(float4*)(Hp + (size_t)i * UE + 4) = *(float4*)(out + 4);
    }
}

// ---------------------------------------------------------------------------
// Level-0 gates: g0[t,b,:16] = softmax(x@gw0[t] + gb0[t]),
//                gs[b,:40]   = softmax(x@gws + gbs)
// One block per batch row, 128 threads.
// ---------------------------------------------------------------------------
__global__ __launch_bounds__(128) void gates0(const float* __restrict__ x,
                                              const float* __restrict__ gw0,
                                              const float* __restrict__ gb0,
                                              const float* __restrict__ gws,
                                              const float* __restrict__ gbs) {
    const int b   = blockIdx.x;
    const int tid = threadIdx.x;
    __shared__ float sx[D_];
    __shared__ float sz[NG0];

    const float4* xr = (const float4*)(x + (size_t)b * D_);
    ((float4*)sx)[tid]       = xr[tid];
    ((float4*)sx)[tid + 128] = xr[tid + 128];
    __syncthreads();

    if (tid < 64) {
        const int t = tid >> 4, j = tid & 15;
        const float* W = gw0 + (size_t)t * D_ * 16 + j;
        float acc = gb0[t * 16 + j];
#pragma unroll 8
        for (int k = 0; k < D_; k++) acc += sx[k] * W[(size_t)k * 16];
        sz[tid] = acc;
    } else if (tid < NG0) {
        const int j = tid - 64;
        const float* W = gws + j;
        float acc = gbs[j];
#pragma unroll 8
        for (int k = 0; k < D_; k++) acc += sx[k] * W[(size_t)k * 40];
        sz[tid] = acc;
    }
    __syncthreads();

    if (tid < 64) {
        const int t = tid >> 4, j = tid & 15;
        float m = -1e30f;
        for (int i = 0; i < 16; i++) m = fmaxf(m, sz[t * 16 + i]);
        float s = 0.f;
        for (int i = 0; i < 16; i++) s += expf(sz[t * 16 + i] - m);
        g_g0[((size_t)t * B_ + b) * 16 + j] = expf(sz[tid] - m) / s;
    } else if (tid < NG0) {
        float m = -1e30f;
        for (int i = 0; i < 40; i++) m = fmaxf(m, sz[64 + i]);
        float s = 0.f;
        for (int i = 0; i < 40; i++) s += expf(sz[64 + i] - m);
        g_gs[(size_t)b * 40 + (tid - 64)] = expf(sz[tid] - m) / s;
    }
}

// ---------------------------------------------------------------------------
// Level-0 combine: gate-weighted reductions over expert axis (E=8) producing
// task_out0 (T,B,U) and share_out (B,U).
// ---------------------------------------------------------------------------
__global__ __launch_bounds__(512) void combine0() {
    const int b = blockIdx.x;
    const int u = threadIdx.x;   // 512 threads
    __shared__ float sg0[4][16];
    __shared__ float sgs[40];
    if (threadIdx.x < 64) {
        const int t = threadIdx.x >> 4, j = threadIdx.x & 15;
        sg0[t][j] = g_g0[((size_t)t * B_ + b) * 16 + j];
    } else if (threadIdx.x < 104) {
        sgs[threadIdx.x - 64] = g_gs[(size_t)b * 40 + (threadIdx.x - 64)];
    }
    __syncthreads();

    float h[5][8];
#pragma unroll
    for (int t = 0; t < 5; t++) {
        const float* p = g_H + ((size_t)t * B_ + b) * UE + (u << 3);
        *(float4*)(h[t])     = *(const float4*)(p);
        *(float4*)(h[t] + 4) = *(const float4*)(p + 4);
    }

    float sh = 0.f;
#pragma unroll
    for (int t = 0; t < 4; t++) {
        float to = 0.f;
#pragma unroll
        for (int e = 0; e < 8; e++) {
            to += h[t][e] * sg0[t][e] + h[4][e] * sg0[t][8 + e];
            sh += h[t][e] * sgs[t * 8 + e];
        }
        g_task0[((size_t)t * B_ + b) * U_ + u] = to;
    }
#pragma unroll
    for (int e = 0; e < 8; e++) sh += h[4][e] * sgs[32 + e];
    g_share[(size_t)b * U_ + u] = sh;
}

// ---------------------------------------------------------------------------
// Level-1 gates: g1[t,b,:16] = softmax(task_out0[t,b] @ gw1[t] + gb1[t])
// ---------------------------------------------------------------------------
__global__ __launch_bounds__(128) void gates1(const float* __restrict__ gw1,
                                              const float* __restrict__ gb1) {
    const int b   = blockIdx.x;
    const int tid = threadIdx.x;
    __shared__ float sin_[4][U_];
    __shared__ float sz[64];

    for (int i = tid; i < 512; i += 128) {    // 512 float4 = 4 rows of 512 floats
        const int t = i >> 7;
        const int o = i & 127;
        ((float4*)sin_)[i] = ((const float4*)(g_task0 + ((size_t)t * B_ + b) * U_))[o];
    }
    __syncthreads();

    if (tid < 64) {
        const int t = tid >> 4, j = tid & 15;
        const float* W = gw1 + (size_t)t * U_ * 16 + j;
        float acc = gb1[t * 16 + j];
#pragma unroll 8
        for (int k = 0; k < U_; k++) acc += sin_[t][k] * W[(size_t)k * 16];
        sz[tid] = acc;
    }
    __syncthreads();

    if (tid < 64) {
        const int t = tid >> 4, j = tid & 15;
        float m = -1e30f;
        for (int i = 0; i < 16; i++) m = fmaxf(m, sz[t * 16 + i]);
        float s = 0.f;
        for (int i = 0; i < 16; i++) s += expf(sz[t * 16 + i] - m);
        g_g1[((size_t)t * B_ + b) * 16 + j] = expf(sz[tid] - m) / s;
    }
}

// ---------------------------------------------------------------------------
// Level-1 combine: final output (T,B,U)
// ---------------------------------------------------------------------------
__global__ __launch_bounds__(512) void combine1(float* __restrict__ out) {
    const int b = blockIdx.x;
    const int u = threadIdx.x;
    __shared__ float sg[4][16];
    if (threadIdx.x < 64) {
        const int t = threadIdx.x >> 4, j = threadIdx.x & 15;
        sg[t][j] = g_g1[((size_t)t * B_ + b) * 16 + j];
    }
    __syncthreads();

    float h[5][8];
#pragma unroll
    for (int t = 0; t < 5; t++) {
        const float* p = g_H + ((size_t)t * B_ + b) * UE + (u << 3);
        *(float4*)(h[t])     = *(const float4*)(p);
        *(float4*)(h[t] + 4) = *(const float4*)(p + 4);
    }
#pragma unroll
    for (int t = 0; t < 4; t++) {
        float o = 0.f;
#pragma unroll
        for (int e = 0; e < 8; e++)
            o += h[t][e] * sg[t][e] + h[4][e] * sg[t][8 + e];
        out[((size_t)t * B_ + b) * U_ + u] = o;
    }
}

// ---------------------------------------------------------------------------
// Launch
// ---------------------------------------------------------------------------
extern "C" void kernel_launch(void* const* d_in, const int* in_sizes, int n_in,
                              void* d_out, int out_size) {
    (void)in_sizes; (void)n_in; (void)out_size;
    const float* x    = (const float*)d_in[0];
    const float* ews0 = (const float*)d_in[1];
    const float* ebs0 = (const float*)d_in[2];
    const float* ews1 = (const float*)d_in[3];
    const float* ebs1 = (const float*)d_in[4];
    const float* gws  = (const float*)d_in[5];
    const float* gbs  = (const float*)d_in[6];
    const float* ew0  = (const float*)d_in[7];
    const float* eb0  = (const float*)d_in[8];
    const float* gw0  = (const float*)d_in[9];
    const float* gb0  = (const float*)d_in[10];
    const float* ew1  = (const float*)d_in[11];
    const float* eb1  = (const float*)d_in[12];
    const float* gw1  = (const float*)d_in[13];
    const float* gb1  = (const float*)d_in[14];

    float *H = nullptr, *task0 = nullptr, *share = nullptr;
    cudaGetSymbolAddress((void**)&H,     g_H);
    cudaGetSymbolAddress((void**)&task0, g_task0);
    cudaGetSymbolAddress((void**)&share, g_share);

    // ---- level 0 ----
    gates0<<<B_, 128>>>(x, gw0, gb0, gws, gbs);

    GemmArgs a0;
    for (int t = 0; t < 5; t++) a0.A[t] = x;
    for (int t = 0; t < 4; t++) {
        a0.Bm[t]   = ew0 + (size_t)t * D_ * UE;
        a0.bias[t] = eb0 + (size_t)t * UE;
    }
    a0.Bm[4] = ews0; a0.bias[4] = ebs0;
    a0.H = H; a0.K = D_;
    expert_gemm<<<dim3(160, 64), 256>>>(a0);

    combine0<<<B_, 512>>>();

    // ---- level 1 ----
    gates1<<<B_, 128>>>(gw1, gb1);

    GemmArgs a1;
    for (int t = 0; t < 4; t++) {
        a1.A[t]    = task0 + (size_t)t * B_ * U_;
        a1.Bm[t]   = ew1 + (size_t)t * U_ * UE;
        a1.bias[t] = eb1 + (size_t)t * UE;
    }
    a1.A[4] = share; a1.Bm[4] = ews1; a1.bias[4] = ebs1;
    a1.H = H; a1.K = U_;
    expert_gemm<<<dim3(160, 64), 256>>>(a1);

    combine1<<<B_, 512>>>((float*)d_out);
}

// round 7
// speedup vs baseline: 1.3479x; 1.3479x over previous
#include <cuda_runtime.h>
#include <cuda_bf16.h>
#include <cstdint>

#define T_  4
#define B_  8192
#define D_  1024
#define U_  512
#define UE  4096
#define NTOT 4096
#define NG0 104

// ---------------------------------------------------------------------------
// Device scratch
// ---------------------------------------------------------------------------
__device__ float g_H[5ull * B_ * UE];                       // expert outputs (both levels)
__device__ __nv_bfloat16 g_xhi[(size_t)B_ * D_];
__device__ __nv_bfloat16 g_xlo[(size_t)B_ * D_];
__device__ __nv_bfloat16 g_bt0h[5ull * NTOT * D_];          // level-0 B^T hi (N-major, K contiguous)
__device__ __nv_bfloat16 g_bt0l[5ull * NTOT * D_];
__device__ __nv_bfloat16 g_bt1h[5ull * NTOT * U_];
__device__ __nv_bfloat16 g_bt1l[5ull * NTOT * U_];
__device__ __nv_bfloat16 g_a1h[5ull * B_ * U_];             // level-1 A hi (4 tasks + share)
__device__ __nv_bfloat16 g_a1l[5ull * B_ * U_];
__device__ float g_g0[(size_t)T_ * B_ * 16];
__device__ float g_gs[(size_t)B_ * 40];
__device__ float g_task0[(size_t)T_ * B_ * U_];             // fp32 (gate input)
__device__ float g_g1[(size_t)T_ * B_ * 16];

// ---------------------------------------------------------------------------
// PTX helpers (baseline sm_80+ instructions only — no arch-conditional ops)
// ---------------------------------------------------------------------------
__device__ __forceinline__ uint32_t smem_u32(const void* p) {
    uint32_t a;
    asm("{ .reg .u64 t; cvta.to.shared.u64 t, %1; cvt.u32.u64 %0, t; }" : "=r"(a) : "l"(p));
    return a;
}
__device__ __forceinline__ void cp16(uint32_t dst, const void* src) {
    asm volatile("cp.async.cg.shared.global [%0], [%1], 16;" :: "r"(dst), "l"(src));
}
__device__ __forceinline__ void ldsm4(uint32_t* r, uint32_t addr) {
    asm volatile("ldmatrix.sync.aligned.m8n8.x4.shared.b16 {%0,%1,%2,%3}, [%4];"
        : "=r"(r[0]), "=r"(r[1]), "=r"(r[2]), "=r"(r[3]) : "r"(addr));
}
__device__ __forceinline__ void mma16816(float* c, const uint32_t* a, uint32_t b0, uint32_t b1) {
    asm volatile("mma.sync.aligned.m16n8k16.row.col.f32.bf16.bf16.f32 "
        "{%0,%1,%2,%3}, {%4,%5,%6,%7}, {%8,%9}, {%0,%1,%2,%3};"
        : "+f"(c[0]), "+f"(c[1]), "+f"(c[2]), "+f"(c[3])
        : "r"(a[0]), "r"(a[1]), "r"(a[2]), "r"(a[3]), "r"(b0), "r"(b1));
}

// ---------------------------------------------------------------------------
// Conversion kernels (fp32 -> bf16 hi/lo split; B transposed to N-major)
// ---------------------------------------------------------------------------
__global__ void convX(const float* __restrict__ x, __nv_bfloat16* __restrict__ hi,
                      __nv_bfloat16* __restrict__ lo) {
    size_t i = (size_t)blockIdx.x * blockDim.x + threadIdx.x;   // per float4
    float4 v = ((const float4*)x)[i];
    __nv_bfloat16 h0 = __float2bfloat16(v.x), h1 = __float2bfloat16(v.y);
    __nv_bfloat16 h2 = __float2bfloat16(v.z), h3 = __float2bfloat16(v.w);
    __nv_bfloat16 l0 = __float2bfloat16(v.x - __bfloat162float(h0));
    __nv_bfloat16 l1 = __float2bfloat16(v.y - __bfloat162float(h1));
    __nv_bfloat16 l2 = __float2bfloat16(v.z - __bfloat162float(h2));
    __nv_bfloat16 l3 = __float2bfloat16(v.w - __bfloat162float(h3));
    ((__nv_bfloat162*)hi)[2 * i]     = __nv_bfloat162(h0, h1);
    ((__nv_bfloat162*)hi)[2 * i + 1] = __nv_bfloat162(h2, h3);
    ((__nv_bfloat162*)lo)[2 * i]     = __nv_bfloat162(l0, l1);
    ((__nv_bfloat162*)lo)[2 * i + 1] = __nv_bfloat162(l2, l3);
}

struct ConvBArgs { const float* src[5]; __nv_bfloat16* hi; __nv_bfloat16* lo; int K; };

__global__ void convB(ConvBArgs a) {
    __shared__ float s[32][33];
    const int z = blockIdx.z;
    const float* __restrict__ src = a.src[z];
    const int n0 = blockIdx.x * 32, k0 = blockIdx.y * 32;
    const int tx = threadIdx.x, ty = threadIdx.y;   // (32, 8)
#pragma unroll
    for (int i = 0; i < 4; i++)
        s[ty + i * 8][tx] = src[(size_t)(k0 + ty + i * 8) * UE + n0 + tx];
    __syncthreads();
    __nv_bfloat16* oh = a.hi + (size_t)z * NTOT * a.K;
    __nv_bfloat16* ol = a.lo + (size_t)z * NTOT * a.K;
#pragma unroll
    for (int i = 0; i < 4; i++) {
        const int n = n0 + ty + i * 8, k = k0 + tx;
        float v = s[tx][ty + i * 8];
        __nv_bfloat16 h = __float2bfloat16(v);
        __nv_bfloat16 l = __float2bfloat16(v - __bfloat162float(h));
        oh[(size_t)n * a.K + k] = h;
        ol[(size_t)n * a.K + k] = l;
    }
}

// ---------------------------------------------------------------------------
// Tensor-core expert GEMM via warp-level mma.sync (bf16, 3-term split).
// CTA 128x128, K-step 32, 8 warps (32x64 each), double-buffered cp.async.
// SMEM rows padded to 80B -> conflict-free ldmatrix without swizzle.
// ---------------------------------------------------------------------------
struct TGemmArgs {
    const __nv_bfloat16 *Ah[5], *Al[5], *Bh[5], *Bl[5];
    const float* bias[5];
    float* H;
    int K;
};

#define KSTEP 32
#define MAT_BYTES 10240        // 128 rows * 80 bytes
#define STAGE_BYTES (4 * MAT_BYTES)
#define SMEM_BYTES (2 * STAGE_BYTES)   // 81920

__global__ __launch_bounds__(256, 2) void mma_gemm(TGemmArgs args) {
    extern __shared__ __align__(128) char smem[];
    const uint32_t sb = smem_u32(smem);
    const int t  = blockIdx.x >> 5;
    const int n0 = (blockIdx.x & 31) << 7;
    const int m0 = blockIdx.y << 7;
    const int K  = args.K;
    const int nk = K / KSTEP;
    const int tid  = threadIdx.x;
    const int lane = tid & 31;
    const int w    = tid >> 5;
    const int wm   = w & 3;          // 0..3 -> m offset 32*wm
    const int wn   = w >> 2;         // 0..1 -> n offset 64*wn

    const __nv_bfloat16* __restrict__ srcs[4] = {
        args.Ah[t] + (size_t)m0 * K, args.Al[t] + (size_t)m0 * K,
        args.Bh[t] + (size_t)n0 * K, args.Bl[t] + (size_t)n0 * K };

    auto load_stage = [&](int buf, int kc) {
        const uint32_t base = sb + buf * STAGE_BYTES;
#pragma unroll
        for (int i = 0; i < 8; i++) {
            const int mat = i >> 1;                       // compile-time per unroll
            const int r   = ((i & 1) << 6) + (tid >> 2);  // 0..127
            const int ch  = tid & 3;                      // 16B chunk in 64B row
            cp16(base + mat * MAT_BYTES + r * 80 + ch * 16,
                 srcs[mat] + (size_t)r * K + kc + ch * 8);
        }
        asm volatile("cp.async.commit_group;" ::: "memory");
    };

    float acc[2][8][4];
#pragma unroll
    for (int i = 0; i < 2; i++)
#pragma unroll
        for (int j = 0; j < 8; j++)
#pragma unroll
            for (int q = 0; q < 4; q++) acc[i][j][q] = 0.f;

    load_stage(0, 0);

    // fragment address offsets (bytes)
    const uint32_t arow_off = (uint32_t)((32 * wm + (lane & 15)) * 80 + ((lane >> 4) << 4));
    const uint32_t brow     = (uint32_t)(64 * wn + (((lane >> 3) & 1) << 3) + (lane & 7));
    const uint32_t brow_off = brow * 80 + ((uint32_t)(lane >> 4) << 4);

    for (int c = 0; c < nk; c++) {
        asm volatile("cp.async.wait_group 0;" ::: "memory");
        __syncthreads();
        if (c + 1 < nk) load_stage((c + 1) & 1, (c + 1) * KSTEP);

        const uint32_t st = sb + (c & 1) * STAGE_BYTES;
        const uint32_t aH = st;
        const uint32_t aL = st + MAT_BYTES;
        const uint32_t bH = st + 2 * MAT_BYTES;
        const uint32_t bL = st + 3 * MAT_BYTES;

#pragma unroll
        for (int ks = 0; ks < 2; ks++) {
            const uint32_t ko = ks * 32;   // 16 bf16 = 32 bytes per k16 sub-step
            uint32_t ahi[2][4], alo[2][4];
#pragma unroll
            for (int i = 0; i < 2; i++) {
                ldsm4(ahi[i], aH + arow_off + i * (16 * 80) + ko);
                ldsm4(alo[i], aL + arow_off + i * (16 * 80) + ko);
            }
            uint32_t bf[4][4];
#pragma unroll
            for (int j = 0; j < 4; j++) ldsm4(bf[j], bH + brow_off + j * (16 * 80) + ko);
#pragma unroll
            for (int i = 0; i < 2; i++)
#pragma unroll
                for (int j = 0; j < 4; j++) {
                    mma16816(acc[i][2 * j],     ahi[i], bf[j][0], bf[j][2]);
                    mma16816(acc[i][2 * j + 1], ahi[i], bf[j][1], bf[j][3]);
                    mma16816(acc[i][2 * j],     alo[i], bf[j][0], bf[j][2]);
                    mma16816(acc[i][2 * j + 1], alo[i], bf[j][1], bf[j][3]);
                }
#pragma unroll
            for (int j = 0; j < 4; j++) ldsm4(bf[j], bL + brow_off + j * (16 * 80) + ko);
#pragma unroll
            for (int i = 0; i < 2; i++)
#pragma unroll
                for (int j = 0; j < 4; j++) {
                    mma16816(acc[i][2 * j],     ahi[i], bf[j][0], bf[j][2]);
                    mma16816(acc[i][2 * j + 1], ahi[i], bf[j][1], bf[j][3]);
                }
        }
    }

    // epilogue: bias + relu, direct store
    const float* __restrict__ bias = args.bias[t];
    float* __restrict__ Hb = args.H + (size_t)t * B_ * UE;
#pragma unroll
    for (int i = 0; i < 2; i++) {
        const int mr = m0 + 32 * wm + 16 * i + (lane >> 2);
#pragma unroll
        for (int j = 0; j < 8; j++) {
            const int nc = n0 + 64 * wn + 8 * j + ((lane & 3) << 1);
            const float b0v = bias[nc], b1v = bias[nc + 1];
            float2 o0, o1;
            o0.x = fmaxf(acc[i][j][0] + b0v, 0.f);
            o0.y = fmaxf(acc[i][j][1] + b1v, 0.f);
            o1.x = fmaxf(acc[i][j][2] + b0v, 0.f);
            o1.y = fmaxf(acc[i][j][3] + b1v, 0.f);
            *(float2*)(Hb + (size_t)mr * UE + nc)       = o0;
            *(float2*)(Hb + (size_t)(mr + 8) * UE + nc) = o1;
        }
    }
}

// ---------------------------------------------------------------------------
// Gates / combines (fp32) — unchanged from the verified R5 kernel
// ---------------------------------------------------------------------------
__global__ __launch_bounds__(128) void gates0(const float* __restrict__ x,
                                              const float* __restrict__ gw0,
                                              const float* __restrict__ gb0,
                                              const float* __restrict__ gws,
                                              const float* __restrict__ gbs) {
    const int b = blockIdx.x, tid = threadIdx.x;
    __shared__ float sx[D_];
    __shared__ float sz[NG0];
    const float4* xr = (const float4*)(x + (size_t)b * D_);
    ((float4*)sx)[tid] = xr[tid];
    ((float4*)sx)[tid + 128] = xr[tid + 128];
    __syncthreads();
    if (tid < 64) {
        const int t = tid >> 4, j = tid & 15;
        const float* W = gw0 + (size_t)t * D_ * 16 + j;
        float acc = gb0[t * 16 + j];
#pragma unroll 8
        for (int k = 0; k < D_; k++) acc += sx[k] * W[(size_t)k * 16];
        sz[tid] = acc;
    } else if (tid < NG0) {
        const int j = tid - 64;
        const float* W = gws + j;
        float acc = gbs[j];
#pragma unroll 8
        for (int k = 0; k < D_; k++) acc += sx[k] * W[(size_t)k * 40];
        sz[tid] = acc;
    }
    __syncthreads();
    if (tid < 64) {
        const int t = tid >> 4, j = tid & 15;
        float mx = -1e30f;
        for (int i = 0; i < 16; i++) mx = fmaxf(mx, sz[t * 16 + i]);
        float s = 0.f;
        for (int i = 0; i < 16; i++) s += expf(sz[t * 16 + i] - mx);
        g_g0[((size_t)t * B_ + b) * 16 + j] = expf(sz[tid] - mx) / s;
    } else if (tid < NG0) {
        float mx = -1e30f;
        for (int i = 0; i < 40; i++) mx = fmaxf(mx, sz[64 + i]);
        float s = 0.f;
        for (int i = 0; i < 40; i++) s += expf(sz[64 + i] - mx);
        g_gs[(size_t)b * 40 + (tid - 64)] = expf(sz[tid] - mx) / s;
    }
}

__global__ __launch_bounds__(512) void combine0() {
    const int b = blockIdx.x;
    const int u = threadIdx.x;
    __shared__ float sg0[4][16];
    __shared__ float sgs[40];
    if (threadIdx.x < 64) {
        const int t = threadIdx.x >> 4, j = threadIdx.x & 15;
        sg0[t][j] = g_g0[((size_t)t * B_ + b) * 16 + j];
    } else if (threadIdx.x < 104) {
        sgs[threadIdx.x - 64] = g_gs[(size_t)b * 40 + (threadIdx.x - 64)];
    }
    __syncthreads();

    float h[5][8];
#pragma unroll
    for (int t = 0; t < 5; t++) {
        const float* p = g_H + ((size_t)t * B_ + b) * UE + (u << 3);
        *(float4*)(h[t]) = *(const float4*)(p);
        *(float4*)(h[t] + 4) = *(const float4*)(p + 4);
    }

    float sh = 0.f;
#pragma unroll
    for (int t = 0; t < 4; t++) {
        float to = 0.f;
#pragma unroll
        for (int e = 0; e < 8; e++) {
            to += h[t][e] * sg0[t][e] + h[4][e] * sg0[t][8 + e];
            sh += h[t][e] * sgs[t * 8 + e];
        }
        g_task0[((size_t)t * B_ + b) * U_ + u] = to;
        __nv_bfloat16 hh = __float2bfloat16(to);
        g_a1h[((size_t)t * B_ + b) * U_ + u] = hh;
        g_a1l[((size_t)t * B_ + b) * U_ + u] = __float2bfloat16(to - __bfloat162float(hh));
    }
#pragma unroll
    for (int e = 0; e < 8; e++) sh += h[4][e] * sgs[32 + e];
    __nv_bfloat16 hs = __float2bfloat16(sh);
    g_a1h[((size_t)4 * B_ + b) * U_ + u] = hs;
    g_a1l[((size_t)4 * B_ + b) * U_ + u] = __float2bfloat16(sh - __bfloat162float(hs));
}

__global__ __launch_bounds__(128) void gates1(const float* __restrict__ gw1,
                                              const float* __restrict__ gb1) {
    const int b = blockIdx.x, tid = threadIdx.x;
    __shared__ float sin_[4][U_];
    __shared__ float sz[64];
    for (int i = tid; i < 512; i += 128) {
        const int t = i >> 7, o = i & 127;
        ((float4*)sin_)[i] = ((const float4*)(g_task0 + ((size_t)t * B_ + b) * U_))[o];
    }
    __syncthreads();
    if (tid < 64) {
        const int t = tid >> 4, j = tid & 15;
        const float* W = gw1 + (size_t)t * U_ * 16 + j;
        float acc = gb1[t * 16 + j];
#pragma unroll 8
        for (int k = 0; k < U_; k++) acc += sin_[t][k] * W[(size_t)k * 16];
        sz[tid] = acc;
    }
    __syncthreads();
    if (tid < 64) {
        const int t = tid >> 4, j = tid & 15;
        float mx = -1e30f;
        for (int i = 0; i < 16; i++) mx = fmaxf(mx, sz[t * 16 + i]);
        float s = 0.f;
        for (int i = 0; i < 16; i++) s += expf(sz[t * 16 + i] - mx);
        g_g1[((size_t)t * B_ + b) * 16 + j] = expf(sz[tid] - mx) / s;
    }
}

__global__ __launch_bounds__(512) void combine1(float* __restrict__ out) {
    const int b = blockIdx.x;
    const int u = threadIdx.x;
    __shared__ float sg[4][16];
    if (threadIdx.x < 64) {
        const int t = threadIdx.x >> 4, j = threadIdx.x & 15;
        sg[t][j] = g_g1[((size_t)t * B_ + b) * 16 + j];
    }
    __syncthreads();
    float h[5][8];
#pragma unroll
    for (int t = 0; t < 5; t++) {
        const float* p = g_H + ((size_t)t * B_ + b) * UE + (u << 3);
        *(float4*)(h[t]) = *(const float4*)(p);
        *(float4*)(h[t] + 4) = *(const float4*)(p + 4);
    }
#pragma unroll
    for (int t = 0; t < 4; t++) {
        float o = 0.f;
#pragma unroll
        for (int e = 0; e < 8; e++)
            o += h[t][e] * sg[t][e] + h[4][e] * sg[t][8 + e];
        out[((size_t)t * B_ + b) * U_ + u] = o;
    }
}

// ---------------------------------------------------------------------------
// Launch
// ---------------------------------------------------------------------------
extern "C" void kernel_launch(void* const* d_in, const int* in_sizes, int n_in,
                              void* d_out, int out_size) {
    (void)in_sizes; (void)n_in; (void)out_size;
    const float* x    = (const float*)d_in[0];
    const float* ews0 = (const float*)d_in[1];
    const float* ebs0 = (const float*)d_in[2];
    const float* ews1 = (const float*)d_in[3];
    const float* ebs1 = (const float*)d_in[4];
    const float* gws  = (const float*)d_in[5];
    const float* gbs  = (const float*)d_in[6];
    const float* ew0  = (const float*)d_in[7];
    const float* eb0  = (const float*)d_in[8];
    const float* gw0  = (const float*)d_in[9];
    const float* gb0  = (const float*)d_in[10];
    const float* ew1  = (const float*)d_in[11];
    const float* eb1  = (const float*)d_in[12];
    const float* gw1  = (const float*)d_in[13];
    const float* gb1  = (const float*)d_in[14];

    cudaFuncSetAttribute(mma_gemm, cudaFuncAttributeMaxDynamicSharedMemorySize, SMEM_BYTES);

    float* H; cudaGetSymbolAddress((void**)&H, g_H);
    __nv_bfloat16 *xhi, *xlo, *bt0h, *bt0l, *bt1h, *bt1l, *a1h, *a1l;
    cudaGetSymbolAddress((void**)&xhi,  g_xhi);
    cudaGetSymbolAddress((void**)&xlo,  g_xlo);
    cudaGetSymbolAddress((void**)&bt0h, g_bt0h);
    cudaGetSymbolAddress((void**)&bt0l, g_bt0l);
    cudaGetSymbolAddress((void**)&bt1h, g_bt1h);
    cudaGetSymbolAddress((void**)&bt1l, g_bt1l);
    cudaGetSymbolAddress((void**)&a1h,  g_a1h);
    cudaGetSymbolAddress((void**)&a1l,  g_a1l);

    // conversions
    convX<<<(B_ * D_ / 4) / 256, 256>>>(x, xhi, xlo);
    ConvBArgs cb0;
    for (int t = 0; t < 4; t++) cb0.src[t] = ew0 + (size_t)t * D_ * UE;
    cb0.src[4] = ews0; cb0.hi = bt0h; cb0.lo = bt0l; cb0.K = D_;
    convB<<<dim3(NTOT / 32, D_ / 32, 5), dim3(32, 8)>>>(cb0);
    ConvBArgs cb1;
    for (int t = 0; t < 4; t++) cb1.src[t] = ew1 + (size_t)t * U_ * UE;
    cb1.src[4] = ews1; cb1.hi = bt1h; cb1.lo = bt1l; cb1.K = U_;
    convB<<<dim3(NTOT / 32, U_ / 32, 5), dim3(32, 8)>>>(cb1);

    // level 0
    gates0<<<B_, 128>>>(x, gw0, gb0, gws, gbs);
    TGemmArgs a0;
    for (int t = 0; t < 5; t++) { a0.Ah[t] = xhi; a0.Al[t] = xlo; }
    for (int t = 0; t < 5; t++) {
        a0.Bh[t] = bt0h + (size_t)t * NTOT * D_;
        a0.Bl[t] = bt0l + (size_t)t * NTOT * D_;
    }
    for (int t = 0; t < 4; t++) a0.bias[t] = eb0 + (size_t)t * UE;
    a0.bias[4] = ebs0;
    a0.H = H; a0.K = D_;
    mma_gemm<<<dim3(160, 64), 256, SMEM_BYTES>>>(a0);
    combine0<<<B_, 512>>>();

    // level 1
    gates1<<<B_, 128>>>(gw1, gb1);
    TGemmArgs a1;
    for (int t = 0; t < 5; t++) {
        a1.Ah[t] = a1h + (size_t)t * B_ * U_;
        a1.Al[t] = a1l + (size_t)t * B_ * U_;
        a1.Bh[t] = bt1h + (size_t)t * NTOT * U_;
        a1.Bl[t] = bt1l + (size_t)t * NTOT * U_;
    }
    for (int t = 0; t < 4; t++) a1.bias[t] = eb1 + (size_t)t * UE;
    a1.bias[4] = ebs1;
    a1.H = H; a1.K = U_;
    mma_gemm<<<dim3(160, 64), 256, SMEM_BYTES>>>(a1);
    combine1<<<B_, 512>>>((float*)d_out);
}

// round 8
// speedup vs baseline: 2.4176x; 1.7936x over previous
#include <cuda_runtime.h>
#include <cuda_bf16.h>
#include <cstdint>

#define T_  4
#define B_  8192
#define D_  1024
#define U_  512
#define UE  4096
#define NTOT 4096

// ---------------------------------------------------------------------------
// Device scratch
// ---------------------------------------------------------------------------
__device__ float g_H[5ull * B_ * UE];
__device__ __nv_bfloat16 g_xhi[(size_t)B_ * D_];
__device__ __nv_bfloat16 g_xlo[(size_t)B_ * D_];
__device__ __nv_bfloat16 g_bt0h[5ull * NTOT * D_];
__device__ __nv_bfloat16 g_bt0l[5ull * NTOT * D_];
__device__ __nv_bfloat16 g_bt1h[5ull * NTOT * U_];
__device__ __nv_bfloat16 g_bt1l[5ull * NTOT * U_];
__device__ __nv_bfloat16 g_a1h[5ull * B_ * U_];
__device__ __nv_bfloat16 g_a1l[5ull * B_ * U_];
__device__ float g_g0[(size_t)T_ * B_ * 16];
__device__ float g_gs[(size_t)B_ * 40];
__device__ float g_task0[(size_t)T_ * B_ * U_];
__device__ float g_g1[(size_t)T_ * B_ * 16];

// ---------------------------------------------------------------------------
// PTX helpers (baseline sm_80+ only)
// ---------------------------------------------------------------------------
__device__ __forceinline__ uint32_t smem_u32(const void* p) {
    uint32_t a;
    asm("{ .reg .u64 t; cvta.to.shared.u64 t, %1; cvt.u32.u64 %0, t; }" : "=r"(a) : "l"(p));
    return a;
}
__device__ __forceinline__ void cp16(uint32_t dst, const void* src) {
    asm volatile("cp.async.cg.shared.global [%0], [%1], 16;" :: "r"(dst), "l"(src));
}
__device__ __forceinline__ void ldsm4(uint32_t* r, uint32_t addr) {
    asm volatile("ldmatrix.sync.aligned.m8n8.x4.shared.b16 {%0,%1,%2,%3}, [%4];"
        : "=r"(r[0]), "=r"(r[1]), "=r"(r[2]), "=r"(r[3]) : "r"(addr));
}
__device__ __forceinline__ void mma16816(float* c, const uint32_t* a, uint32_t b0, uint32_t b1) {
    asm volatile("mma.sync.aligned.m16n8k16.row.col.f32.bf16.bf16.f32 "
        "{%0,%1,%2,%3}, {%4,%5,%6,%7}, {%8,%9}, {%0,%1,%2,%3};"
        : "+f"(c[0]), "+f"(c[1]), "+f"(c[2]), "+f"(c[3])
        : "r"(a[0]), "r"(a[1]), "r"(a[2]), "r"(a[3]), "r"(b0), "r"(b1));
}

// ---------------------------------------------------------------------------
// Conversions (fp32 -> bf16 hi/lo; B transposed to N-major)
// ---------------------------------------------------------------------------
__global__ void convX(const float* __restrict__ x, __nv_bfloat16* __restrict__ hi,
                      __nv_bfloat16* __restrict__ lo) {
    size_t i = (size_t)blockIdx.x * blockDim.x + threadIdx.x;
    float4 v = ((const float4*)x)[i];
    __nv_bfloat16 h0 = __float2bfloat16(v.x), h1 = __float2bfloat16(v.y);
    __nv_bfloat16 h2 = __float2bfloat16(v.z), h3 = __float2bfloat16(v.w);
    __nv_bfloat16 l0 = __float2bfloat16(v.x - __bfloat162float(h0));
    __nv_bfloat16 l1 = __float2bfloat16(v.y - __bfloat162float(h1));
    __nv_bfloat16 l2 = __float2bfloat16(v.z - __bfloat162float(h2));
    __nv_bfloat16 l3 = __float2bfloat16(v.w - __bfloat162float(h3));
    ((__nv_bfloat162*)hi)[2 * i]     = __nv_bfloat162(h0, h1);
    ((__nv_bfloat162*)hi)[2 * i + 1] = __nv_bfloat162(h2, h3);
    ((__nv_bfloat162*)lo)[2 * i]     = __nv_bfloat162(l0, l1);
    ((__nv_bfloat162*)lo)[2 * i + 1] = __nv_bfloat162(l2, l3);
}

struct ConvBArgs { const float* src[5]; __nv_bfloat16* hi; __nv_bfloat16* lo; int K; };

__global__ void convB(ConvBArgs a) {
    __shared__ float s[32][33];
    const int z = blockIdx.z;
    const float* __restrict__ src = a.src[z];
    const int n0 = blockIdx.x * 32, k0 = blockIdx.y * 32;
    const int tx = threadIdx.x, ty = threadIdx.y;
#pragma unroll
    for (int i = 0; i < 4; i++)
        s[ty + i * 8][tx] = src[(size_t)(k0 + ty + i * 8) * UE + n0 + tx];
    __syncthreads();
    __nv_bfloat16* oh = a.hi + (size_t)z * NTOT * a.K;
    __nv_bfloat16* ol = a.lo + (size_t)z * NTOT * a.K;
#pragma unroll
    for (int i = 0; i < 4; i++) {
        const int n = n0 + ty + i * 8, k = k0 + tx;
        float v = s[tx][ty + i * 8];
        __nv_bfloat16 h = __float2bfloat16(v);
        __nv_bfloat16 l = __float2bfloat16(v - __bfloat162float(h));
        oh[(size_t)n * a.K + k] = h;
        ol[(size_t)n * a.K + k] = l;
    }
}

// ---------------------------------------------------------------------------
// GEMM: 128x128 tile, K-step 32, 3-stage cp.async, 64B rows + XOR swizzle,
// 8 warps (32x64 each), bf16 3-term split. L2-aware rasterization.
// ---------------------------------------------------------------------------
struct TGemmArgs {
    const __nv_bfloat16 *Ah[5], *Al[5], *Bh[5], *Bl[5];
    const float* bias[5];
    float* H;
    int K;
};

#define KSTEP 32
#define MAT_BYTES 8192                 // 128 rows * 64B
#define STAGE_BYTES (4 * MAT_BYTES)    // 32 KB
#define NSTAGE 3
#define SMEM_BYTES (NSTAGE * STAGE_BYTES)  // 96 KB

__global__ __launch_bounds__(256, 2) void mma_gemm(TGemmArgs args) {
    extern __shared__ __align__(128) char smem[];
    const uint32_t sb = smem_u32(smem);

    // L2-aware rasterization: 16 consecutive CTAs share one (t, n0) B tile.
    const int id    = blockIdx.x;          // 0..10239
    const int group = id / 2560;           // 16*160
    const int rem   = id - group * 2560;
    const int mt    = group * 16 + (rem & 15);
    const int ntid  = rem >> 4;            // 0..159
    const int t     = ntid >> 5;
    const int n0    = (ntid & 31) << 7;
    const int m0    = mt << 7;

    const int K  = args.K;
    const int nk = K / KSTEP;
    const int tid  = threadIdx.x;
    const int lane = tid & 31;
    const int w    = tid >> 5;
    const int wm   = w & 3;
    const int wn   = w >> 2;
    const int hb   = lane >> 4;

    const __nv_bfloat16* __restrict__ srcs[4] = {
        args.Ah[t] + (size_t)m0 * K, args.Al[t] + (size_t)m0 * K,
        args.Bh[t] + (size_t)n0 * K, args.Bl[t] + (size_t)n0 * K };

    // cooperative load mapping
    const int rlo  = tid >> 2;             // row within 64-row half
    const int ch   = tid & 3;              // 16B chunk
    const int dsw  = ((ch ^ ((rlo >> 1) & 3)) << 4);

    auto load_stage = [&](int buf, int kc) {
        const uint32_t base = sb + (uint32_t)buf * STAGE_BYTES;
#pragma unroll
        for (int i = 0; i < 8; i++) {
            const int mat = i >> 1;
            const int r   = ((i & 1) << 6) + rlo;
            cp16(base + mat * MAT_BYTES + r * 64 + dsw,
                 srcs[mat] + (size_t)r * K + kc + ch * 8);
        }
        asm volatile("cp.async.commit_group;" ::: "memory");
    };

    // fragment smem offsets (per thread, per k16-substep)
    uint32_t aoff[2][2], boff[4][2];
#pragma unroll
    for (int i = 0; i < 2; i++) {
        const int rA = 32 * wm + 16 * i + (lane & 15);
        const int csw = (rA >> 1) & 3;
#pragma unroll
        for (int ks = 0; ks < 2; ks++)
            aoff[i][ks] = (uint32_t)(rA * 64 + (((2 * ks + hb) ^ csw) << 4));
    }
#pragma unroll
    for (int j = 0; j < 4; j++) {
        const int rB = 64 * wn + 16 * j + (((lane >> 3) & 1) << 3) + (lane & 7);
        const int csw = (rB >> 1) & 3;
#pragma unroll
        for (int ks = 0; ks < 2; ks++)
            boff[j][ks] = (uint32_t)(rB * 64 + (((2 * ks + hb) ^ csw) << 4));
    }

    float acc[2][8][4];
#pragma unroll
    for (int i = 0; i < 2; i++)
#pragma unroll
        for (int j = 0; j < 8; j++)
#pragma unroll
            for (int q = 0; q < 4; q++) acc[i][j][q] = 0.f;

    load_stage(0, 0);
    load_stage(1, KSTEP);

    for (int c = 0; c < nk; c++) {
        if (c + 1 < nk) asm volatile("cp.async.wait_group 1;" ::: "memory");
        else            asm volatile("cp.async.wait_group 0;" ::: "memory");
        __syncthreads();
        if (c + 2 < nk) {
            int nb = c + 2; while (nb >= NSTAGE) nb -= NSTAGE;
            load_stage(nb, (c + 2) * KSTEP);
        }
        int cb = c; while (cb >= NSTAGE) cb -= NSTAGE;
        const uint32_t st = sb + (uint32_t)cb * STAGE_BYTES;

#pragma unroll
        for (int ks = 0; ks < 2; ks++) {
            uint32_t ahi[2][4], alo[2][4];
#pragma unroll
            for (int i = 0; i < 2; i++) {
                ldsm4(ahi[i], st + aoff[i][ks]);
                ldsm4(alo[i], st + MAT_BYTES + aoff[i][ks]);
            }
            uint32_t bf[4][4];
#pragma unroll
            for (int j = 0; j < 4; j++) ldsm4(bf[j], st + 2 * MAT_BYTES + boff[j][ks]);
#pragma unroll
            for (int i = 0; i < 2; i++)
#pragma unroll
                for (int j = 0; j < 4; j++) {
                    mma16816(acc[i][2 * j],     ahi[i], bf[j][0], bf[j][2]);
                    mma16816(acc[i][2 * j + 1], ahi[i], bf[j][1], bf[j][3]);
                    mma16816(acc[i][2 * j],     alo[i], bf[j][0], bf[j][2]);
                    mma16816(acc[i][2 * j + 1], alo[i], bf[j][1], bf[j][3]);
                }
#pragma unroll
            for (int j = 0; j < 4; j++) ldsm4(bf[j], st + 3 * MAT_BYTES + boff[j][ks]);
#pragma unroll
            for (int i = 0; i < 2; i++)
#pragma unroll
                for (int j = 0; j < 4; j++) {
                    mma16816(acc[i][2 * j],     ahi[i], bf[j][0], bf[j][2]);
                    mma16816(acc[i][2 * j + 1], ahi[i], bf[j][1], bf[j][3]);
                }
        }
    }

    // epilogue: bias + relu
    const float* __restrict__ bias = args.bias[t];
    float* __restrict__ Hb = args.H + (size_t)t * B_ * UE;
#pragma unroll
    for (int i = 0; i < 2; i++) {
        const int mr = m0 + 32 * wm + 16 * i + (lane >> 2);
#pragma unroll
        for (int j = 0; j < 8; j++) {
            const int nc = n0 + 64 * wn + 8 * j + ((lane & 3) << 1);
            const float b0v = bias[nc], b1v = bias[nc + 1];
            float2 o0, o1;
            o0.x = fmaxf(acc[i][j][0] + b0v, 0.f);
            o0.y = fmaxf(acc[i][j][1] + b1v, 0.f);
            o1.x = fmaxf(acc[i][j][2] + b0v, 0.f);
            o1.y = fmaxf(acc[i][j][3] + b1v, 0.f);
            *(float2*)(Hb + (size_t)mr * UE + nc)       = o0;
            *(float2*)(Hb + (size_t)(mr + 8) * UE + nc) = o1;
        }
    }
}

// ---------------------------------------------------------------------------
// gates0: 16 batch rows per CTA, weights amortized 16x, float4 LDS.
// z[b, 0..63] task logits, z[b, 64..103] shared logits; softmax per group.
// ---------------------------------------------------------------------------
__global__ __launch_bounds__(256) void gates0(const float* __restrict__ x,
                                              const float* __restrict__ gw0,
                                              const float* __restrict__ gb0,
                                              const float* __restrict__ gws,
                                              const float* __restrict__ gbs) {
    const int b0 = blockIdx.x * 16;
    const int tid = threadIdx.x;
    __shared__ float sx[16][128];
    __shared__ float sz[16][104];

    const bool active = tid < 208;
    const int rh = (tid >= 104) ? 1 : 0;
    const int c  = active ? (tid - rh * 104) : 0;

    const float* Wp; int wstride;
    if (c < 64) { Wp = gw0 + (size_t)(c >> 4) * D_ * 16 + (c & 15); wstride = 16; }
    else        { Wp = gws + (c - 64);                              wstride = 40; }

    float acc[8];
#pragma unroll
    for (int r = 0; r < 8; r++) acc[r] = 0.f;

    for (int kc = 0; kc < D_ / 128; kc++) {
        __syncthreads();
#pragma unroll
        for (int p = 0; p < 2; p++) {
            const int idx = tid + p * 256;
            const int row = idx >> 5, c4 = idx & 31;
            *(float4*)&sx[row][c4 * 4] =
                *(const float4*)(x + (size_t)(b0 + row) * D_ + kc * 128 + c4 * 4);
        }
        __syncthreads();
        if (active) {
            const float* wp = Wp + (size_t)kc * 128 * wstride;
#pragma unroll 4
            for (int k = 0; k < 128; k += 4) {
                const float w0 = wp[(k + 0) * wstride];
                const float w1 = wp[(k + 1) * wstride];
                const float w2 = wp[(k + 2) * wstride];
                const float w3 = wp[(k + 3) * wstride];
#pragma unroll
                for (int r = 0; r < 8; r++) {
                    float4 xv = *(const float4*)&sx[rh * 8 + r][k];
                    acc[r] += xv.x * w0 + xv.y * w1 + xv.z * w2 + xv.w * w3;
                }
            }
        }
    }
    if (active) {
        const float bb = (c < 64) ? gb0[c] : gbs[c - 64];
#pragma unroll
        for (int r = 0; r < 8; r++) sz[rh * 8 + r][c] = acc[r] + bb;
    }
    __syncthreads();

    if (tid < 80) {
        const int r = tid & 15, g = tid >> 4;
        const int base = (g < 4) ? g * 16 : 64;
        const int len  = (g < 4) ? 16 : 40;
        float mx = -1e30f;
        for (int i = 0; i < len; i++) mx = fmaxf(mx, sz[r][base + i]);
        float s = 0.f;
        for (int i = 0; i < len; i++) s += expf(sz[r][base + i] - mx);
        const float inv = 1.f / s;
        if (g < 4) {
            float* o = g_g0 + ((size_t)g * B_ + b0 + r) * 16;
            for (int i = 0; i < 16; i++) o[i] = expf(sz[r][base + i] - mx) * inv;
        } else {
            float* o = g_gs + (size_t)(b0 + r) * 40;
            for (int i = 0; i < 40; i++) o[i] = expf(sz[r][base + i] - mx) * inv;
        }
    }
}

// ---------------------------------------------------------------------------
// gates1: 16 rows per CTA, per-task inputs from g_task0.
// ---------------------------------------------------------------------------
__global__ __launch_bounds__(256) void gates1(const float* __restrict__ gw1,
                                              const float* __restrict__ gb1) {
    const int b0 = blockIdx.x * 16;
    const int tid = threadIdx.x;
    __shared__ float s1[4][16][128];
    __shared__ float sz[16][64];

    const bool active = tid < 128;
    const int rh = (tid >> 6) & 1;
    const int c  = tid & 63;
    const int tt = c >> 4;
    const float* Wp = gw1 + (size_t)tt * U_ * 16 + (c & 15);

    float acc[8];
#pragma unroll
    for (int r = 0; r < 8; r++) acc[r] = 0.f;

    for (int kc = 0; kc < U_ / 128; kc++) {
        __syncthreads();
#pragma unroll
        for (int p = 0; p < 8; p++) {
            const int idx = tid + p * 256;
            const int tz = idx >> 9, row = (idx >> 5) & 15, c4 = idx & 31;
            *(float4*)&s1[tz][row][c4 * 4] =
                *(const float4*)(g_task0 + ((size_t)tz * B_ + b0 + row) * U_ + kc * 128 + c4 * 4);
        }
        __syncthreads();
        if (active) {
            const float* wp = Wp + (size_t)kc * 128 * 16;
#pragma unroll 4
            for (int k = 0; k < 128; k += 4) {
                const float w0 = wp[(k + 0) * 16];
                const float w1 = wp[(k + 1) * 16];
                const float w2 = wp[(k + 2) * 16];
                const float w3 = wp[(k + 3) * 16];
#pragma unroll
                for (int r = 0; r < 8; r++) {
                    float4 xv = *(const float4*)&s1[tt][rh * 8 + r][k];
                    acc[r] += xv.x * w0 + xv.y * w1 + xv.z * w2 + xv.w * w3;
                }
            }
        }
    }
    if (active) {
        const float bb = gb1[c];
#pragma unroll
        for (int r = 0; r < 8; r++) sz[rh * 8 + r][c] = acc[r] + bb;
    }
    __syncthreads();

    if (tid < 64) {
        const int r = tid & 15, g = tid >> 4;
        float mx = -1e30f;
        for (int i = 0; i < 16; i++) mx = fmaxf(mx, sz[r][g * 16 + i]);
        float s = 0.f;
        for (int i = 0; i < 16; i++) s += expf(sz[r][g * 16 + i] - mx);
        const float inv = 1.f / s;
        float* o = g_g1 + ((size_t)g * B_ + b0 + r) * 16;
        for (int i = 0; i < 16; i++) o[i] = expf(sz[r][g * 16 + i] - mx) * inv;
    }
}

// ---------------------------------------------------------------------------
// Combines
// ---------------------------------------------------------------------------
__global__ __launch_bounds__(512) void combine0() {
    const int b = blockIdx.x;
    const int u = threadIdx.x;
    __shared__ float sg0[4][16];
    __shared__ float sgs[40];
    if (threadIdx.x < 64) {
        const int t = threadIdx.x >> 4, j = threadIdx.x & 15;
        sg0[t][j] = g_g0[((size_t)t * B_ + b) * 16 + j];
    } else if (threadIdx.x < 104) {
        sgs[threadIdx.x - 64] = g_gs[(size_t)b * 40 + (threadIdx.x - 64)];
    }
    __syncthreads();

    float h[5][8];
#pragma unroll
    for (int t = 0; t < 5; t++) {
        const float* p = g_H + ((size_t)t * B_ + b) * UE + (u << 3);
        *(float4*)(h[t]) = *(const float4*)(p);
        *(float4*)(h[t] + 4) = *(const float4*)(p + 4);
    }

    float sh = 0.f;
#pragma unroll
    for (int t = 0; t < 4; t++) {
        float to = 0.f;
#pragma unroll
        for (int e = 0; e < 8; e++) {
            to += h[t][e] * sg0[t][e] + h[4][e] * sg0[t][8 + e];
            sh += h[t][e] * sgs[t * 8 + e];
        }
        g_task0[((size_t)t * B_ + b) * U_ + u] = to;
        __nv_bfloat16 hh = __float2bfloat16(to);
        g_a1h[((size_t)t * B_ + b) * U_ + u] = hh;
        g_a1l[((size_t)t * B_ + b) * U_ + u] = __float2bfloat16(to - __bfloat162float(hh));
    }
#pragma unroll
    for (int e = 0; e < 8; e++) sh += h[4][e] * sgs[32 + e];
    __nv_bfloat16 hs = __float2bfloat16(sh);
    g_a1h[((size_t)4 * B_ + b) * U_ + u] = hs;
    g_a1l[((size_t)4 * B_ + b) * U_ + u] = __float2bfloat16(sh - __bfloat162float(hs));
}

__global__ __launch_bounds__(512) void combine1(float* __restrict__ out) {
    const int b = blockIdx.x;
    const int u = threadIdx.x;
    __shared__ float sg[4][16];
    if (threadIdx.x < 64) {
        const int t = threadIdx.x >> 4, j = threadIdx.x & 15;
        sg[t][j] = g_g1[((size_t)t * B_ + b) * 16 + j];
    }
    __syncthreads();
    float h[5][8];
#pragma unroll
    for (int t = 0; t < 5; t++) {
        const float* p = g_H + ((size_t)t * B_ + b) * UE + (u << 3);
        *(float4*)(h[t]) = *(const float4*)(p);
        *(float4*)(h[t] + 4) = *(const float4*)(p + 4);
    }
#pragma unroll
    for (int t = 0; t < 4; t++) {
        float o = 0.f;
#pragma unroll
        for (int e = 0; e < 8; e++)
            o += h[t][e] * sg[t][e] + h[4][e] * sg[t][8 + e];
        out[((size_t)t * B_ + b) * U_ + u] = o;
    }
}

// ---------------------------------------------------------------------------
// Launch
// ---------------------------------------------------------------------------
extern "C" void kernel_launch(void* const* d_in, const int* in_sizes, int n_in,
                              void* d_out, int out_size) {
    (void)in_sizes; (void)n_in; (void)out_size;
    const float* x    = (const float*)d_in[0];
    const float* ews0 = (const float*)d_in[1];
    const float* ebs0 = (const float*)d_in[2];
    const float* ews1 = (const float*)d_in[3];
    const float* ebs1 = (const float*)d_in[4];
    const float* gws  = (const float*)d_in[5];
    const float* gbs  = (const float*)d_in[6];
    const float* ew0  = (const float*)d_in[7];
    const float* eb0  = (const float*)d_in[8];
    const float* gw0  = (const float*)d_in[9];
    const float* gb0  = (const float*)d_in[10];
    const float* ew1  = (const float*)d_in[11];
    const float* eb1  = (const float*)d_in[12];
    const float* gw1  = (const float*)d_in[13];
    const float* gb1  = (const float*)d_in[14];

    cudaFuncSetAttribute(mma_gemm, cudaFuncAttributeMaxDynamicSharedMemorySize, SMEM_BYTES);

    float* H; cudaGetSymbolAddress((void**)&H, g_H);
    __nv_bfloat16 *xhi, *xlo, *bt0h, *bt0l, *bt1h, *bt1l, *a1h, *a1l;
    cudaGetSymbolAddress((void**)&xhi,  g_xhi);
    cudaGetSymbolAddress((void**)&xlo,  g_xlo);
    cudaGetSymbolAddress((void**)&bt0h, g_bt0h);
    cudaGetSymbolAddress((void**)&bt0l, g_bt0l);
    cudaGetSymbolAddress((void**)&bt1h, g_bt1h);
    cudaGetSymbolAddress((void**)&bt1l, g_bt1l);
    cudaGetSymbolAddress((void**)&a1h,  g_a1h);
    cudaGetSymbolAddress((void**)&a1l,  g_a1l);

    // conversions
    convX<<<(B_ * D_ / 4) / 256, 256>>>(x, xhi, xlo);
    ConvBArgs cb0;
    for (int t = 0; t < 4; t++) cb0.src[t] = ew0 + (size_t)t * D_ * UE;
    cb0.src[4] = ews0; cb0.hi = bt0h; cb0.lo = bt0l; cb0.K = D_;
    convB<<<dim3(NTOT / 32, D_ / 32, 5), dim3(32, 8)>>>(cb0);
    ConvBArgs cb1;
    for (int t = 0; t < 4; t++) cb1.src[t] = ew1 + (size_t)t * U_ * UE;
    cb1.src[4] = ews1; cb1.hi = bt1h; cb1.lo = bt1l; cb1.K = U_;
    convB<<<dim3(NTOT / 32, U_ / 32, 5), dim3(32, 8)>>>(cb1);

    // level 0
    gates0<<<B_ / 16, 256>>>(x, gw0, gb0, gws, gbs);
    TGemmArgs a0;
    for (int t = 0; t < 5; t++) { a0.Ah[t] = xhi; a0.Al[t] = xlo; }
    for (int t = 0; t < 5; t++) {
        a0.Bh[t] = bt0h + (size_t)t * NTOT * D_;
        a0.Bl[t] = bt0l + (size_t)t * NTOT * D_;
    }
    for (int t = 0; t < 4; t++) a0.bias[t] = eb0 + (size_t)t * UE;
    a0.bias[4] = ebs0;
    a0.H = H; a0.K = D_;
    mma_gemm<<<10240, 256, SMEM_BYTES>>>(a0);
    combine0<<<B_, 512>>>();

    // level 1
    gates1<<<B_ / 16, 256>>>(gw1, gb1);
    TGemmArgs a1;
    for (int t = 0; t < 5; t++) {
        a1.Ah[t] = a1h + (size_t)t * B_ * U_;
        a1.Al[t] = a1l + (size_t)t * B_ * U_;
        a1.Bh[t] = bt1h + (size_t)t * NTOT * U_;
        a1.Bl[t] = bt1l + (size_t)t * NTOT * U_;
    }
    for (int t = 0; t < 4; t++) a1.bias[t] = eb1 + (size_t)t * UE;
    a1.bias[4] = ebs1;
    a1.H = H; a1.K = U_;
    mma_gemm<<<10240, 256, SMEM_BYTES>>>(a1);
    combine1<<<B_, 512>>>((float*)d_out);
}